// round 2
// baseline (speedup 1.0000x reference)
#include <cuda_runtime.h>
#include <cuda_bf16.h>

// Problem constants
#define B_    2
#define N_    2048
#define C_    256
#define COOR  3
#define H_    8
#define D_    64
#define E_    192      // D_*COOR
#define DI    512      // dim_inner = H_*D_
#define BN    4096     // B_*N_
#define BH    16       // B_*H_

// Scratch (device globals — no runtime allocation)
__device__ float g_xt[(size_t)COOR * BN * C_];     //  3.1M floats
__device__ float g_q [(size_t)BH * N_ * E_];       //  6.3M
__device__ float g_k [(size_t)BH * N_ * E_];
__device__ float g_v [(size_t)BH * N_ * E_];
__device__ float g_s [(size_t)BH * N_ * N_];       // 67.1M floats = 256MB
__device__ float g_o2[(size_t)COOR * BN * DI];     //  6.3M

// ---------------------------------------------------------------------------
// Kernel 0: pack x (B,N,C,3) -> xt[c][m][i]  (coalesced writes)
// ---------------------------------------------------------------------------
__global__ __launch_bounds__(256) void transpose_x_kernel(const float* __restrict__ x) {
    int idx = blockIdx.x * 256 + threadIdx.x;           // over COOR*BN*C_
    if (idx < COOR * BN * C_) {
        int i = idx % C_;
        int m = (idx / C_) % BN;
        int c = idx / (C_ * BN);
        g_xt[idx] = x[((size_t)m * C_ + i) * COOR + c];
    }
}

// ---------------------------------------------------------------------------
// Kernel 1: QKV projection.  Out[m][o] = sum_i xt_c[m][i] * W[o][i]
// grid: (BN/64, DI/64, 9)   z -> mat = z/3, c = z%3
// Epilogue scatters into (b,h,n, d*3+c) head layout.
// ---------------------------------------------------------------------------
__global__ __launch_bounds__(256) void qkv_kernel(const float* __restrict__ Wq,
                                                  const float* __restrict__ Wk,
                                                  const float* __restrict__ Wv) {
    int z   = blockIdx.z;
    int mat = z / 3, c = z % 3;
    const float* W = (mat == 0) ? Wq : (mat == 1) ? Wk : Wv;
    float*       G = (mat == 0) ? g_q : (mat == 1) ? g_k : g_v;
    const float* A = g_xt + (size_t)c * BN * C_;

    __shared__ float As[32][65];
    __shared__ float Bs[32][65];

    int m0 = blockIdx.x * 64, o0 = blockIdx.y * 64;
    int tid = threadIdx.x;
    int tm = tid >> 4, to = tid & 15;

    float acc[4][4];
#pragma unroll
    for (int i = 0; i < 4; i++)
#pragma unroll
        for (int j = 0; j < 4; j++) acc[i][j] = 0.f;

    for (int kk = 0; kk < C_; kk += 32) {
#pragma unroll
        for (int r = tid; r < 2048; r += 256) {
            int mm = r >> 5, k = r & 31;
            As[k][mm] = A[(size_t)(m0 + mm) * C_ + kk + k];
            Bs[k][mm] = W[(size_t)(o0 + mm) * C_ + kk + k];
        }
        __syncthreads();
#pragma unroll
        for (int k = 0; k < 32; k++) {
            float a[4], b[4];
#pragma unroll
            for (int i = 0; i < 4; i++) a[i] = As[k][tm + 16 * i];
#pragma unroll
            for (int j = 0; j < 4; j++) b[j] = Bs[k][to + 16 * j];
#pragma unroll
            for (int i = 0; i < 4; i++)
#pragma unroll
                for (int j = 0; j < 4; j++) acc[i][j] = fmaf(a[i], b[j], acc[i][j]);
        }
        __syncthreads();
    }

#pragma unroll
    for (int i = 0; i < 4; i++) {
        int m  = m0 + tm + 16 * i;
        int bb = m >> 11, n = m & (N_ - 1);
#pragma unroll
        for (int j = 0; j < 4; j++) {
            int o = o0 + to + 16 * j;
            int h = o >> 6, d = o & 63;
            G[(size_t)((bb * H_ + h) * N_ + n) * E_ + d * COOR + c] = acc[i][j];
        }
    }
}

// ---------------------------------------------------------------------------
// Kernel 2: S = scale * Q K^T   per bh.  grid: (32, 32, 16)
// ---------------------------------------------------------------------------
__global__ __launch_bounds__(256) void score_kernel() {
    int bh = blockIdx.z;
    const float* Q  = g_q + (size_t)bh * N_ * E_;
    const float* Kp = g_k + (size_t)bh * N_ * E_;
    float*       S  = g_s + (size_t)bh * N_ * N_;

    __shared__ float As[32][65];
    __shared__ float Bs[32][65];

    int i0 = blockIdx.x * 64, j0 = blockIdx.y * 64;
    int tid = threadIdx.x;
    int tm = tid >> 4, to = tid & 15;

    float acc[4][4];
#pragma unroll
    for (int i = 0; i < 4; i++)
#pragma unroll
        for (int j = 0; j < 4; j++) acc[i][j] = 0.f;

    for (int kk = 0; kk < E_; kk += 32) {
#pragma unroll
        for (int r = tid; r < 2048; r += 256) {
            int mm = r >> 5, k = r & 31;
            As[k][mm] = Q [(size_t)(i0 + mm) * E_ + kk + k];
            Bs[k][mm] = Kp[(size_t)(j0 + mm) * E_ + kk + k];
        }
        __syncthreads();
#pragma unroll
        for (int k = 0; k < 32; k++) {
            float a[4], b[4];
#pragma unroll
            for (int i = 0; i < 4; i++) a[i] = As[k][tm + 16 * i];
#pragma unroll
            for (int j = 0; j < 4; j++) b[j] = Bs[k][to + 16 * j];
#pragma unroll
            for (int i = 0; i < 4; i++)
#pragma unroll
                for (int j = 0; j < 4; j++) acc[i][j] = fmaf(a[i], b[j], acc[i][j]);
        }
        __syncthreads();
    }

    const float scale = 0.07216878364870323f;  // 192^-0.5
#pragma unroll
    for (int i = 0; i < 4; i++) {
        int ii = i0 + tm + 16 * i;
#pragma unroll
        for (int j = 0; j < 4; j++) {
            S[(size_t)ii * N_ + j0 + to + 16 * j] = acc[i][j] * scale;
        }
    }
}

// ---------------------------------------------------------------------------
// Kernel 3: row softmax over N_ keys, row kept in registers (8 vals/thread)
// grid: BH*N_ blocks of 256
// ---------------------------------------------------------------------------
__global__ __launch_bounds__(256) void softmax_kernel() {
    __shared__ float red[8];
    __shared__ float bval;
    size_t row = blockIdx.x;
    float* Srow = g_s + row * (size_t)N_;
    int tid = threadIdx.x;
    int lane = tid & 31, w = tid >> 5;

    float v[8];
    float mx = -1e30f;
#pragma unroll
    for (int j = 0; j < 8; j++) { v[j] = Srow[tid + 256 * j]; mx = fmaxf(mx, v[j]); }
#pragma unroll
    for (int o = 16; o; o >>= 1) mx = fmaxf(mx, __shfl_xor_sync(0xffffffffu, mx, o));
    if (lane == 0) red[w] = mx;
    __syncthreads();
    if (tid == 0) {
        float m2 = red[0];
#pragma unroll
        for (int i = 1; i < 8; i++) m2 = fmaxf(m2, red[i]);
        bval = m2;
    }
    __syncthreads();
    mx = bval;

    float s = 0.f;
#pragma unroll
    for (int j = 0; j < 8; j++) { v[j] = __expf(v[j] - mx); s += v[j]; }
#pragma unroll
    for (int o = 16; o; o >>= 1) s += __shfl_xor_sync(0xffffffffu, s, o);
    __syncthreads();
    if (lane == 0) red[w] = s;
    __syncthreads();
    if (tid == 0) {
        float t = 0.f;
#pragma unroll
        for (int i = 0; i < 8; i++) t += red[i];
        bval = 1.f / t;
    }
    __syncthreads();
    float inv = bval;
#pragma unroll
    for (int j = 0; j < 8; j++) Srow[tid + 256 * j] = v[j] * inv;
}

// ---------------------------------------------------------------------------
// Kernel 4: O = P @ V  per bh.  grid: (32, 3, 16).  Epilogue scatters into
// g_o2[c][m][h*64+d] for the final projection GEMM.
// ---------------------------------------------------------------------------
__global__ __launch_bounds__(256) void pv_kernel() {
    int bh = blockIdx.z;
    const float* P = g_s + (size_t)bh * N_ * N_;
    const float* V = g_v + (size_t)bh * N_ * E_;

    __shared__ float As[32][65];
    __shared__ float Bs[32][65];

    int i0 = blockIdx.x * 64, e0 = blockIdx.y * 64;
    int tid = threadIdx.x;
    int tm = tid >> 4, to = tid & 15;

    float acc[4][4];
#pragma unroll
    for (int i = 0; i < 4; i++)
#pragma unroll
        for (int j = 0; j < 4; j++) acc[i][j] = 0.f;

    for (int kk = 0; kk < N_; kk += 32) {
#pragma unroll
        for (int r = tid; r < 2048; r += 256) {
            int mm = r >> 5, k = r & 31;
            As[k][mm] = P[(size_t)(i0 + mm) * N_ + kk + k];
        }
#pragma unroll
        for (int r = tid; r < 2048; r += 256) {
            int k = r >> 6, ee = r & 63;
            Bs[k][ee] = V[(size_t)(kk + k) * E_ + e0 + ee];
        }
        __syncthreads();
#pragma unroll
        for (int k = 0; k < 32; k++) {
            float a[4], b[4];
#pragma unroll
            for (int i = 0; i < 4; i++) a[i] = As[k][tm + 16 * i];
#pragma unroll
            for (int j = 0; j < 4; j++) b[j] = Bs[k][to + 16 * j];
#pragma unroll
            for (int i = 0; i < 4; i++)
#pragma unroll
                for (int j = 0; j < 4; j++) acc[i][j] = fmaf(a[i], b[j], acc[i][j]);
        }
        __syncthreads();
    }

    int b = bh >> 3, h = bh & 7;
#pragma unroll
    for (int i = 0; i < 4; i++) {
        int ii = i0 + tm + 16 * i;
        int m  = b * N_ + ii;
#pragma unroll
        for (int j = 0; j < 4; j++) {
            int e  = e0 + to + 16 * j;     // e = d*3 + c
            int c  = e % 3;
            int dd = e / 3;
            g_o2[((size_t)c * BN + m) * DI + h * 64 + dd] = acc[i][j];
        }
    }
}

// ---------------------------------------------------------------------------
// Kernel 5: final projection.  y_c[m][o'] = sum_i o2_c[m][i] * Wo[o'][i]
// grid: (64, 4, 3).  Writes directly to d_out (B,N,C,3).
// ---------------------------------------------------------------------------
__global__ __launch_bounds__(256) void out_kernel(const float* __restrict__ Wo,
                                                  float* __restrict__ out) {
    int c = blockIdx.z;
    const float* A = g_o2 + (size_t)c * BN * DI;

    __shared__ float As[32][65];
    __shared__ float Bs[32][65];

    int m0 = blockIdx.x * 64, o0 = blockIdx.y * 64;
    int tid = threadIdx.x;
    int tm = tid >> 4, to = tid & 15;

    float acc[4][4];
#pragma unroll
    for (int i = 0; i < 4; i++)
#pragma unroll
        for (int j = 0; j < 4; j++) acc[i][j] = 0.f;

    for (int kk = 0; kk < DI; kk += 32) {
#pragma unroll
        for (int r = tid; r < 2048; r += 256) {
            int mm = r >> 5, k = r & 31;
            As[k][mm] = A [(size_t)(m0 + mm) * DI + kk + k];
            Bs[k][mm] = Wo[(size_t)(o0 + mm) * DI + kk + k];
        }
        __syncthreads();
#pragma unroll
        for (int k = 0; k < 32; k++) {
            float a[4], b[4];
#pragma unroll
            for (int i = 0; i < 4; i++) a[i] = As[k][tm + 16 * i];
#pragma unroll
            for (int j = 0; j < 4; j++) b[j] = Bs[k][to + 16 * j];
#pragma unroll
            for (int i = 0; i < 4; i++)
#pragma unroll
                for (int j = 0; j < 4; j++) acc[i][j] = fmaf(a[i], b[j], acc[i][j]);
        }
        __syncthreads();
    }

#pragma unroll
    for (int i = 0; i < 4; i++) {
        int m = m0 + tm + 16 * i;
#pragma unroll
        for (int j = 0; j < 4; j++) {
            int o = o0 + to + 16 * j;
            out[((size_t)m * C_ + o) * COOR + c] = acc[i][j];
        }
    }
}

// ---------------------------------------------------------------------------
extern "C" void kernel_launch(void* const* d_in, const int* in_sizes, int n_in,
                              void* d_out, int out_size) {
    const float* x  = (const float*)d_in[0];
    const float* Wq = (const float*)d_in[1];
    const float* Wk = (const float*)d_in[2];
    const float* Wv = (const float*)d_in[3];
    const float* Wo = (const float*)d_in[4];
    float* out = (float*)d_out;

    // 0. pack x
    {
        int total = COOR * BN * C_;
        transpose_x_kernel<<<(total + 255) / 256, 256>>>(x);
    }
    // 1. QKV projections
    {
        dim3 grid(BN / 64, DI / 64, 9);
        qkv_kernel<<<grid, 256>>>(Wq, Wk, Wv);
    }
    // 2. scores
    {
        dim3 grid(N_ / 64, N_ / 64, BH);
        score_kernel<<<grid, 256>>>();
    }
    // 3. softmax
    {
        softmax_kernel<<<BH * N_, 256>>>();
    }
    // 4. P @ V
    {
        dim3 grid(N_ / 64, E_ / 64, BH);
        pv_kernel<<<grid, 256>>>();
    }
    // 5. output projection
    {
        dim3 grid(BN / 64, C_ / 64, COOR);
        out_kernel<<<grid, 256>>>(Wo, out);
    }
}

// round 3
// speedup vs baseline: 1.0395x; 1.0395x over previous
#include <cuda_runtime.h>
#include <cuda_bf16.h>
#include <cstdint>

// Problem constants
#define B_    2
#define N_    2048
#define C_    256
#define COOR  3
#define H_    8
#define D_    64
#define E_    192      // D_*COOR
#define DI    512      // dim_inner = H_*D_
#define BN    4096     // B_*N_
#define BH    16       // B_*H_

// Scratch (device globals — no runtime allocation)
__device__ float g_xt[(size_t)COOR * BN * C_];
__device__ float g_q [(size_t)BH * N_ * E_];
__device__ float g_k [(size_t)BH * N_ * E_];
__device__ float g_v [(size_t)BH * N_ * E_];
__device__ float g_s [(size_t)BH * N_ * N_];       // 256 MB
__device__ float g_o2[(size_t)COOR * BN * DI];

// ---------------------------------------------------------------------------
// tf32 helpers
// ---------------------------------------------------------------------------
__device__ __forceinline__ float tf32_rn(float x) {
    uint32_t u;
    asm("cvt.rna.tf32.f32 %0, %1;" : "=r"(u) : "f"(x));
    return __uint_as_float(u);
}

__device__ __forceinline__ void mma_tf32(float* c, const uint32_t* a, const uint32_t* b) {
    asm volatile(
        "mma.sync.aligned.m16n8k8.row.col.f32.tf32.tf32.f32 "
        "{%0,%1,%2,%3},{%4,%5,%6,%7},{%8,%9},{%0,%1,%2,%3};"
        : "+f"(c[0]), "+f"(c[1]), "+f"(c[2]), "+f"(c[3])
        : "r"(a[0]), "r"(a[1]), "r"(a[2]), "r"(a[3]), "r"(b[0]), "r"(b[1]));
}

// conflict-free swizzle for float2 [16][stride] arrays with stride % 16 == 4
__device__ __forceinline__ int SW(int k, int m) {
    return m ^ (k & 7) ^ ((k & 8) >> 2);
}

// ---------------------------------------------------------------------------
// Core: C[128 x BNT] = A[M,K] * B^T (BTRANS: B is [N][K]; else B is [K][N])
// 256 threads. Warp tile = (128/WARPS_M) x (BNT/WARPS_N).
// acc layout: [MI][NI][4] per-thread, m16n8k8 C fragment mapping.
// 3xTF32 split for ~fp32 accuracy.
// ---------------------------------------------------------------------------
template<int BNT, int WARPS_M, int WARPS_N, bool BTRANS>
__device__ __forceinline__ void gemm_tf32_core(
    const float* __restrict__ A, const float* __restrict__ B,
    int K, int lda, int ldb, int m0, int n0, float* acc)
{
    constexpr int WM = 128 / WARPS_M;
    constexpr int WN = BNT / WARPS_N;
    constexpr int MI = WM / 16;
    constexpr int NI = WN / 8;

    __shared__ float2 As2[16][132];
    __shared__ float2 Bs2[16][BNT + 4];

    const int tid  = threadIdx.x;
    const int lane = tid & 31;
    const int warp = tid >> 5;
    const int g    = lane >> 2;       // groupID
    const int tg   = lane & 3;        // thread in group
    const int wm   = (warp % WARPS_M) * WM;
    const int wn   = (warp / WARPS_M) * WN;

#pragma unroll
    for (int i = 0; i < MI * NI * 4; i++) acc[i] = 0.f;

    for (int kk = 0; kk < K; kk += 16) {
        // ---- stage A tile (128 x 16) ----
#pragma unroll
        for (int it = 0; it < 8; ++it) {
            int linear = tid + 256 * it;
            int m = linear >> 4, k = linear & 15;
            float v  = A[(size_t)(m0 + m) * lda + kk + k];
            float hi = tf32_rn(v);
            As2[k][SW(k, m)] = make_float2(hi, v - hi);
        }
        // ---- stage B tile (BNT x 16) ----
        if (BTRANS) {
#pragma unroll
            for (int it = 0; it < BNT * 16 / 256; ++it) {
                int linear = tid + 256 * it;
                int n = linear >> 4, k = linear & 15;
                float v  = B[(size_t)(n0 + n) * ldb + kk + k];
                float hi = tf32_rn(v);
                Bs2[k][SW(k, n)] = make_float2(hi, v - hi);
            }
        } else {
#pragma unroll
            for (int it = 0; it < BNT * 16 / 256; ++it) {
                int linear = tid + 256 * it;
                int n = linear % BNT, k = linear / BNT;
                float v  = B[(size_t)(kk + k) * ldb + n0 + n];
                float hi = tf32_rn(v);
                Bs2[k][SW(k, n)] = make_float2(hi, v - hi);
            }
        }
        __syncthreads();

#pragma unroll
        for (int kc = 0; kc < 16; kc += 8) {
            uint32_t ahi[MI][4], alo[MI][4], bhi[NI][2], blo[NI][2];
#pragma unroll
            for (int mi = 0; mi < MI; mi++) {
                int mb = wm + mi * 16;
                int k0 = kc + tg, k1 = kc + tg + 4;
                float2 p;
                p = As2[k0][SW(k0, mb + g)];     ahi[mi][0] = __float_as_uint(p.x); alo[mi][0] = __float_as_uint(p.y);
                p = As2[k0][SW(k0, mb + g + 8)]; ahi[mi][1] = __float_as_uint(p.x); alo[mi][1] = __float_as_uint(p.y);
                p = As2[k1][SW(k1, mb + g)];     ahi[mi][2] = __float_as_uint(p.x); alo[mi][2] = __float_as_uint(p.y);
                p = As2[k1][SW(k1, mb + g + 8)]; ahi[mi][3] = __float_as_uint(p.x); alo[mi][3] = __float_as_uint(p.y);
            }
#pragma unroll
            for (int ni = 0; ni < NI; ni++) {
                int nb = wn + ni * 8;
                int k0 = kc + tg, k1 = kc + tg + 4;
                float2 p;
                p = Bs2[k0][SW(k0, nb + g)];     bhi[ni][0] = __float_as_uint(p.x); blo[ni][0] = __float_as_uint(p.y);
                p = Bs2[k1][SW(k1, nb + g)];     bhi[ni][1] = __float_as_uint(p.x); blo[ni][1] = __float_as_uint(p.y);
            }
#pragma unroll
            for (int mi = 0; mi < MI; mi++)
#pragma unroll
                for (int ni = 0; ni < NI; ni++) {
                    float* c = acc + (mi * NI + ni) * 4;
                    mma_tf32(c, ahi[mi], bhi[ni]);
                    mma_tf32(c, ahi[mi], blo[ni]);
                    mma_tf32(c, alo[mi], bhi[ni]);
                }
        }
        __syncthreads();
    }
}

// Per-element index helpers for the C fragment
#define C_ROW(wm_, mi_, r_)  ((wm_) + (mi_) * 16 + g + (((r_) >> 1) & 1) * 8)
#define C_COL(wn_, ni_, r_)  ((wn_) + (ni_) * 8 + tg * 2 + ((r_) & 1))

// ---------------------------------------------------------------------------
// Kernel 0: pack x (B,N,C,3) -> xt[c][m][i]
// ---------------------------------------------------------------------------
__global__ __launch_bounds__(256) void transpose_x_kernel(const float* __restrict__ x) {
    int idx = blockIdx.x * 256 + threadIdx.x;
    if (idx < COOR * BN * C_) {
        int i = idx % C_;
        int m = (idx / C_) % BN;
        int c = idx / (C_ * BN);
        g_xt[idx] = x[((size_t)m * C_ + i) * COOR + c];
    }
}

// ---------------------------------------------------------------------------
// Kernel 1: QKV projection (tensor core). grid (32, 4, 9)
// ---------------------------------------------------------------------------
__global__ __launch_bounds__(256) void qkv_kernel(const float* __restrict__ Wq,
                                                  const float* __restrict__ Wk,
                                                  const float* __restrict__ Wv) {
    int z   = blockIdx.z;
    int mat = z / 3, c = z % 3;
    const float* W = (mat == 0) ? Wq : (mat == 1) ? Wk : Wv;
    float*       G = (mat == 0) ? g_q : (mat == 1) ? g_k : g_v;
    const float* A = g_xt + (size_t)c * BN * C_;

    int m0 = blockIdx.x * 128, n0 = blockIdx.y * 128;
    float acc[4 * 4 * 4];
    gemm_tf32_core<128, 2, 4, true>(A, W, C_, C_, C_, m0, n0, acc);

    const int lane = threadIdx.x & 31, warp = threadIdx.x >> 5;
    const int g = lane >> 2, tg = lane & 3;
    const int wm = (warp % 2) * 64, wn = (warp / 2) * 32;
#pragma unroll
    for (int mi = 0; mi < 4; mi++)
#pragma unroll
        for (int ni = 0; ni < 4; ni++)
#pragma unroll
            for (int r = 0; r < 4; r++) {
                int m = m0 + C_ROW(wm, mi, r);
                int o = n0 + C_COL(wn, ni, r);
                int bb = m >> 11, n = m & (N_ - 1);
                int h = o >> 6, d = o & 63;
                G[(size_t)((bb * H_ + h) * N_ + n) * E_ + d * COOR + c] =
                    acc[(mi * 4 + ni) * 4 + r];
            }
}

// ---------------------------------------------------------------------------
// Kernel 2: S = scale * Q K^T  per bh. grid (16, 16, 16)
// ---------------------------------------------------------------------------
__global__ __launch_bounds__(256) void score_kernel() {
    int bh = blockIdx.z;
    const float* Q  = g_q + (size_t)bh * N_ * E_;
    const float* Kp = g_k + (size_t)bh * N_ * E_;
    float*       S  = g_s + (size_t)bh * N_ * N_;

    int i0 = blockIdx.x * 128, j0 = blockIdx.y * 128;
    float acc[4 * 4 * 4];
    gemm_tf32_core<128, 2, 4, true>(Q, Kp, E_, E_, E_, i0, j0, acc);

    const float scale = 0.07216878364870323f;  // 192^-0.5
    const int lane = threadIdx.x & 31, warp = threadIdx.x >> 5;
    const int g = lane >> 2, tg = lane & 3;
    const int wm = (warp % 2) * 64, wn = (warp / 2) * 32;
#pragma unroll
    for (int mi = 0; mi < 4; mi++)
#pragma unroll
        for (int ni = 0; ni < 4; ni++)
#pragma unroll
            for (int r = 0; r < 4; r++) {
                int ii = i0 + C_ROW(wm, mi, r);
                int jj = j0 + C_COL(wn, ni, r);
                S[(size_t)ii * N_ + jj] = acc[(mi * 4 + ni) * 4 + r] * scale;
            }
}

// ---------------------------------------------------------------------------
// Kernel 3: row softmax (unchanged)
// ---------------------------------------------------------------------------
__global__ __launch_bounds__(256) void softmax_kernel() {
    __shared__ float red[8];
    __shared__ float bval;
    size_t row = blockIdx.x;
    float* Srow = g_s + row * (size_t)N_;
    int tid = threadIdx.x;
    int lane = tid & 31, w = tid >> 5;

    float v[8];
    float mx = -1e30f;
#pragma unroll
    for (int j = 0; j < 8; j++) { v[j] = Srow[tid + 256 * j]; mx = fmaxf(mx, v[j]); }
#pragma unroll
    for (int o = 16; o; o >>= 1) mx = fmaxf(mx, __shfl_xor_sync(0xffffffffu, mx, o));
    if (lane == 0) red[w] = mx;
    __syncthreads();
    if (tid == 0) {
        float m2 = red[0];
#pragma unroll
        for (int i = 1; i < 8; i++) m2 = fmaxf(m2, red[i]);
        bval = m2;
    }
    __syncthreads();
    mx = bval;

    float s = 0.f;
#pragma unroll
    for (int j = 0; j < 8; j++) { v[j] = __expf(v[j] - mx); s += v[j]; }
#pragma unroll
    for (int o = 16; o; o >>= 1) s += __shfl_xor_sync(0xffffffffu, s, o);
    __syncthreads();
    if (lane == 0) red[w] = s;
    __syncthreads();
    if (tid == 0) {
        float t = 0.f;
#pragma unroll
        for (int i = 0; i < 8; i++) t += red[i];
        bval = 1.f / t;
    }
    __syncthreads();
    float inv = bval;
#pragma unroll
    for (int j = 0; j < 8; j++) Srow[tid + 256 * j] = v[j] * inv;
}

// ---------------------------------------------------------------------------
// Kernel 4: O = P @ V  per bh. grid (16, 3, 16). BNT=64, B is [K][N] direct.
// ---------------------------------------------------------------------------
__global__ __launch_bounds__(256) void pv_kernel() {
    int bh = blockIdx.z;
    const float* P = g_s + (size_t)bh * N_ * N_;
    const float* V = g_v + (size_t)bh * N_ * E_;

    int i0 = blockIdx.x * 128, e0 = blockIdx.y * 64;
    float acc[2 * 4 * 4];
    gemm_tf32_core<64, 4, 2, false>(P, V, N_, N_, E_, i0, e0, acc);

    const int lane = threadIdx.x & 31, warp = threadIdx.x >> 5;
    const int g = lane >> 2, tg = lane & 3;
    const int wm = (warp % 4) * 32, wn = (warp / 4) * 32;
    int b = bh >> 3, h = bh & 7;
#pragma unroll
    for (int mi = 0; mi < 2; mi++)
#pragma unroll
        for (int ni = 0; ni < 4; ni++)
#pragma unroll
            for (int r = 0; r < 4; r++) {
                int ii = i0 + C_ROW(wm, mi, r);
                int e  = e0 + C_COL(wn, ni, r);      // e = d*3 + c
                int cc = e % 3;
                int dd = e / 3;
                int m  = b * N_ + ii;
                g_o2[((size_t)cc * BN + m) * DI + h * 64 + dd] =
                    acc[(mi * 4 + ni) * 4 + r];
            }
}

// ---------------------------------------------------------------------------
// Kernel 5: final projection. grid (32, 2, 3). Writes d_out (B,N,C,3).
// ---------------------------------------------------------------------------
__global__ __launch_bounds__(256) void out_kernel(const float* __restrict__ Wo,
                                                  float* __restrict__ out) {
    int c = blockIdx.z;
    const float* A = g_o2 + (size_t)c * BN * DI;

    int m0 = blockIdx.x * 128, o0 = blockIdx.y * 128;
    float acc[4 * 4 * 4];
    gemm_tf32_core<128, 2, 4, true>(A, Wo, DI, DI, DI, m0, o0, acc);

    const int lane = threadIdx.x & 31, warp = threadIdx.x >> 5;
    const int g = lane >> 2, tg = lane & 3;
    const int wm = (warp % 2) * 64, wn = (warp / 2) * 32;
#pragma unroll
    for (int mi = 0; mi < 4; mi++)
#pragma unroll
        for (int ni = 0; ni < 4; ni++)
#pragma unroll
            for (int r = 0; r < 4; r++) {
                int m = m0 + C_ROW(wm, mi, r);
                int o = o0 + C_COL(wn, ni, r);
                out[((size_t)m * C_ + o) * COOR + c] = acc[(mi * 4 + ni) * 4 + r];
            }
}

// ---------------------------------------------------------------------------
extern "C" void kernel_launch(void* const* d_in, const int* in_sizes, int n_in,
                              void* d_out, int out_size) {
    const float* x  = (const float*)d_in[0];
    const float* Wq = (const float*)d_in[1];
    const float* Wk = (const float*)d_in[2];
    const float* Wv = (const float*)d_in[3];
    const float* Wo = (const float*)d_in[4];
    float* out = (float*)d_out;

    {
        int total = COOR * BN * C_;
        transpose_x_kernel<<<(total + 255) / 256, 256>>>(x);
    }
    {
        dim3 grid(BN / 128, DI / 128, 9);
        qkv_kernel<<<grid, 256>>>(Wq, Wk, Wv);
    }
    {
        dim3 grid(N_ / 128, N_ / 128, BH);
        score_kernel<<<grid, 256>>>();
    }
    {
        softmax_kernel<<<BH * N_, 256>>>();
    }
    {
        dim3 grid(N_ / 128, E_ / 64, BH);
        pv_kernel<<<grid, 256>>>();
    }
    {
        dim3 grid(BN / 128, C_ / 128, COOR);
        out_kernel<<<grid, 256>>>(Wo, out);
    }
}

// round 8
// speedup vs baseline: 1.5469x; 1.4881x over previous
#include <cuda_runtime.h>
#include <cuda_fp16.h>
#include <cstdint>

// Problem constants
#define B_    2
#define N_    2048
#define C_    256
#define COOR  3
#define H_    8
#define D_    64
#define E_    192      // D_*COOR
#define DI    512      // dim_inner = H_*D_
#define BN    4096     // B_*N_
#define BH    16       // B_*H_

// Scratch (device globals — no runtime allocation)
__device__ float g_xt[(size_t)COOR * BN * C_];
__device__ float g_q [(size_t)BH * N_ * E_];
__device__ float g_k [(size_t)BH * N_ * E_];
__device__ float g_v [(size_t)BH * N_ * E_];
__device__ float g_s [(size_t)BH * N_ * N_];       // 256 MB
__device__ float g_o2[(size_t)COOR * BN * DI];

// ---------------------------------------------------------------------------
// fp16 helpers
// ---------------------------------------------------------------------------
// Split two adjacent fp32 k-values into packed fp16x2 hi and fp16x2 lo words.
__device__ __forceinline__ uint2 split2h(float2 v) {
    __half hx = __float2half_rn(v.x);
    __half hy = __float2half_rn(v.y);
    float lx = v.x - __half2float(hx);
    float ly = v.y - __half2float(hy);
    __half lxh = __float2half_rn(lx);
    __half lyh = __float2half_rn(ly);
    uint2 r;
    r.x = ((uint32_t)__half_as_ushort(hy) << 16) | (uint32_t)__half_as_ushort(hx);
    r.y = ((uint32_t)__half_as_ushort(lyh) << 16) | (uint32_t)__half_as_ushort(lxh);
    return r;
}

__device__ __forceinline__ void mma_fp16_k16(float* c, const uint32_t* a, const uint32_t* b) {
    asm volatile(
        "mma.sync.aligned.m16n8k16.row.col.f32.f16.f16.f32 "
        "{%0,%1,%2,%3},{%4,%5,%6,%7},{%8,%9},{%0,%1,%2,%3};"
        : "+f"(c[0]), "+f"(c[1]), "+f"(c[2]), "+f"(c[3])
        : "r"(a[0]), "r"(a[1]), "r"(a[2]), "r"(a[3]), "r"(b[0]), "r"(b[1]));
}

// XOR swizzle for uint2 [16][stride] arrays (stride % 16 == 4)
__device__ __forceinline__ int SW(int kp, int m) {
    return m ^ (kp & 7) ^ ((kp & 8) >> 2);
}

// ---------------------------------------------------------------------------
// Core: C[128 x BNT] = A[M,K] * B^T (BTRANS: B is [N][K]; else B is [K][N])
// 256 threads. Warp tile = (128/WARPS_M) x (BNT/WARPS_N).
// fp16 x3 split (hi*hi + hi*lo + lo*hi) with m16n8k16, fp32 accum.
// K staged in chunks of 32.
// ---------------------------------------------------------------------------
template<int BNT, int WARPS_M, int WARPS_N, bool BTRANS>
__device__ __forceinline__ void gemm_fp16x3_core(
    const float* __restrict__ A, const float* __restrict__ B,
    int K, int lda, int ldb, int m0, int n0, float* acc)
{
    constexpr int WM = 128 / WARPS_M;
    constexpr int WN = BNT / WARPS_N;
    constexpr int MI = WM / 16;
    constexpr int NI = WN / 8;

    __shared__ uint2 As2[16][132];          // [k-pair][row]  (hi2, lo2)
    __shared__ uint2 Bs2[16][BNT + 4];

    const int tid  = threadIdx.x;
    const int lane = tid & 31;
    const int warp = tid >> 5;
    const int g    = lane >> 2;       // groupID
    const int tg   = lane & 3;        // thread in group
    const int wm   = (warp % WARPS_M) * WM;
    const int wn   = (warp / WARPS_M) * WN;

#pragma unroll
    for (int i = 0; i < MI * NI * 4; i++) acc[i] = 0.f;

    for (int kk = 0; kk < K; kk += 32) {
        // ---- stage A tile (128 rows x 16 k-pairs) ----
#pragma unroll
        for (int it = 0; it < 8; ++it) {
            int linear = tid + 256 * it;
            int m = linear >> 4, kp = linear & 15;
            float2 v = reinterpret_cast<const float2*>(A + (size_t)(m0 + m) * lda + kk)[kp];
            As2[kp][SW(kp, m)] = split2h(v);
        }
        // ---- stage B tile (BNT x 16 k-pairs) ----
        if (BTRANS) {
#pragma unroll
            for (int it = 0; it < BNT * 16 / 256; ++it) {
                int linear = tid + 256 * it;
                int n = linear >> 4, kp = linear & 15;
                float2 v = reinterpret_cast<const float2*>(B + (size_t)(n0 + n) * ldb + kk)[kp];
                Bs2[kp][SW(kp, n)] = split2h(v);
            }
        } else {
#pragma unroll
            for (int it = 0; it < BNT * 16 / 256; ++it) {
                int linear = tid + 256 * it;
                int n = linear % BNT, kp = linear / BNT;
                float2 v;
                v.x = B[(size_t)(kk + 2 * kp)     * ldb + n0 + n];
                v.y = B[(size_t)(kk + 2 * kp + 1) * ldb + n0 + n];
                Bs2[kp][SW(kp, n)] = split2h(v);
            }
        }
        __syncthreads();

#pragma unroll
        for (int kc = 0; kc < 2; ++kc) {
            const int kp0 = kc * 8 + tg;
            const int kp1 = kc * 8 + tg + 4;
            uint32_t ahi[MI][4], alo[MI][4], bhi[NI][2], blo[NI][2];
#pragma unroll
            for (int mi = 0; mi < MI; mi++) {
                int mb = wm + mi * 16;
                uint2 p;
                p = As2[kp0][SW(kp0, mb + g)];     ahi[mi][0] = p.x; alo[mi][0] = p.y;
                p = As2[kp0][SW(kp0, mb + g + 8)]; ahi[mi][1] = p.x; alo[mi][1] = p.y;
                p = As2[kp1][SW(kp1, mb + g)];     ahi[mi][2] = p.x; alo[mi][2] = p.y;
                p = As2[kp1][SW(kp1, mb + g + 8)]; ahi[mi][3] = p.x; alo[mi][3] = p.y;
            }
#pragma unroll
            for (int ni = 0; ni < NI; ni++) {
                int nb = wn + ni * 8;
                uint2 p;
                p = Bs2[kp0][SW(kp0, nb + g)];     bhi[ni][0] = p.x; blo[ni][0] = p.y;
                p = Bs2[kp1][SW(kp1, nb + g)];     bhi[ni][1] = p.x; blo[ni][1] = p.y;
            }
#pragma unroll
            for (int mi = 0; mi < MI; mi++)
#pragma unroll
                for (int ni = 0; ni < NI; ni++) {
                    float* c = acc + (mi * NI + ni) * 4;
                    mma_fp16_k16(c, ahi[mi], bhi[ni]);
                    mma_fp16_k16(c, ahi[mi], blo[ni]);
                    mma_fp16_k16(c, alo[mi], bhi[ni]);
                }
        }
        __syncthreads();
    }
}

// Per-element index helpers for the C fragment (m16n8k16 == m16n8k8 layout)
#define C_ROW(wm_, mi_, r_)  ((wm_) + (mi_) * 16 + g + (((r_) >> 1) & 1) * 8)
#define C_COL(wn_, ni_, r_)  ((wn_) + (ni_) * 8 + tg * 2 + ((r_) & 1))

// ---------------------------------------------------------------------------
// Kernel 0: pack x (B,N,C,3) -> xt[c][m][i]
// ---------------------------------------------------------------------------
__global__ __launch_bounds__(256) void transpose_x_kernel(const float* __restrict__ x) {
    int idx = blockIdx.x * 256 + threadIdx.x;
    if (idx < COOR * BN * C_) {
        int i = idx % C_;
        int m = (idx / C_) % BN;
        int c = idx / (C_ * BN);
        g_xt[idx] = x[((size_t)m * C_ + i) * COOR + c];
    }
}

// ---------------------------------------------------------------------------
// Kernel 1: QKV projection. grid (32, 4, 9)
// ---------------------------------------------------------------------------
__global__ __launch_bounds__(256) void qkv_kernel(const float* __restrict__ Wq,
                                                  const float* __restrict__ Wk,
                                                  const float* __restrict__ Wv) {
    int z   = blockIdx.z;
    int mat = z / 3, c = z % 3;
    const float* W = (mat == 0) ? Wq : (mat == 1) ? Wk : Wv;
    float*       G = (mat == 0) ? g_q : (mat == 1) ? g_k : g_v;
    const float* A = g_xt + (size_t)c * BN * C_;

    int m0 = blockIdx.x * 128, n0 = blockIdx.y * 128;
    float acc[4 * 4 * 4];
    gemm_fp16x3_core<128, 2, 4, true>(A, W, C_, C_, C_, m0, n0, acc);

    const int lane = threadIdx.x & 31, warp = threadIdx.x >> 5;
    const int g = lane >> 2, tg = lane & 3;
    const int wm = (warp % 2) * 64, wn = (warp / 2) * 32;
#pragma unroll
    for (int mi = 0; mi < 4; mi++)
#pragma unroll
        for (int ni = 0; ni < 4; ni++)
#pragma unroll
            for (int r = 0; r < 4; r++) {
                int m = m0 + C_ROW(wm, mi, r);
                int o = n0 + C_COL(wn, ni, r);
                int bb = m >> 11, n = m & (N_ - 1);
                int h = o >> 6, d = o & 63;
                G[(size_t)((bb * H_ + h) * N_ + n) * E_ + d * COOR + c] =
                    acc[(mi * 4 + ni) * 4 + r];
            }
}

// ---------------------------------------------------------------------------
// Kernel 2: S = scale * Q K^T  per bh. grid (16, 16, 16)
// ---------------------------------------------------------------------------
__global__ __launch_bounds__(256) void score_kernel() {
    int bh = blockIdx.z;
    const float* Q  = g_q + (size_t)bh * N_ * E_;
    const float* Kp = g_k + (size_t)bh * N_ * E_;
    float*       S  = g_s + (size_t)bh * N_ * N_;

    int i0 = blockIdx.x * 128, j0 = blockIdx.y * 128;
    float acc[4 * 4 * 4];
    gemm_fp16x3_core<128, 2, 4, true>(Q, Kp, E_, E_, E_, i0, j0, acc);

    const float scale = 0.07216878364870323f;  // 192^-0.5
    const int lane = threadIdx.x & 31, warp = threadIdx.x >> 5;
    const int g = lane >> 2, tg = lane & 3;
    const int wm = (warp % 2) * 64, wn = (warp / 2) * 32;
#pragma unroll
    for (int mi = 0; mi < 4; mi++)
#pragma unroll
        for (int ni = 0; ni < 4; ni++)
#pragma unroll
            for (int r = 0; r < 4; r++) {
                int ii = i0 + C_ROW(wm, mi, r);
                int jj = j0 + C_COL(wn, ni, r);
                S[(size_t)ii * N_ + jj] = acc[(mi * 4 + ni) * 4 + r] * scale;
            }
}

// ---------------------------------------------------------------------------
// Kernel 3: row softmax
// ---------------------------------------------------------------------------
__global__ __launch_bounds__(256) void softmax_kernel() {
    __shared__ float red[8];
    __shared__ float bval;
    size_t row = blockIdx.x;
    float* Srow = g_s + row * (size_t)N_;
    int tid = threadIdx.x;
    int lane = tid & 31, w = tid >> 5;

    float v[8];
    float mx = -1e30f;
#pragma unroll
    for (int j = 0; j < 8; j++) { v[j] = Srow[tid + 256 * j]; mx = fmaxf(mx, v[j]); }
#pragma unroll
    for (int o = 16; o; o >>= 1) mx = fmaxf(mx, __shfl_xor_sync(0xffffffffu, mx, o));
    if (lane == 0) red[w] = mx;
    __syncthreads();
    if (tid == 0) {
        float m2 = red[0];
#pragma unroll
        for (int i = 1; i < 8; i++) m2 = fmaxf(m2, red[i]);
        bval = m2;
    }
    __syncthreads();
    mx = bval;

    float s = 0.f;
#pragma unroll
    for (int j = 0; j < 8; j++) { v[j] = __expf(v[j] - mx); s += v[j]; }
#pragma unroll
    for (int o = 16; o; o >>= 1) s += __shfl_xor_sync(0xffffffffu, s, o);
    __syncthreads();
    if (lane == 0) red[w] = s;
    __syncthreads();
    if (tid == 0) {
        float t = 0.f;
#pragma unroll
        for (int i = 0; i < 8; i++) t += red[i];
        bval = 1.f / t;
    }
    __syncthreads();
    float inv = bval;
#pragma unroll
    for (int j = 0; j < 8; j++) Srow[tid + 256 * j] = v[j] * inv;
}

// ---------------------------------------------------------------------------
// Kernel 4: O = P @ V  per bh. grid (16, 3, 16). BNT=64, B is [K][N].
// ---------------------------------------------------------------------------
__global__ __launch_bounds__(256) void pv_kernel() {
    int bh = blockIdx.z;
    const float* P = g_s + (size_t)bh * N_ * N_;
    const float* V = g_v + (size_t)bh * N_ * E_;

    int i0 = blockIdx.x * 128, e0 = blockIdx.y * 64;
    float acc[2 * 4 * 4];
    gemm_fp16x3_core<64, 4, 2, false>(P, V, N_, N_, E_, i0, e0, acc);

    const int lane = threadIdx.x & 31, warp = threadIdx.x >> 5;
    const int g = lane >> 2, tg = lane & 3;
    const int wm = (warp % 4) * 32, wn = (warp / 4) * 32;
    int b = bh >> 3, h = bh & 7;
#pragma unroll
    for (int mi = 0; mi < 2; mi++)
#pragma unroll
        for (int ni = 0; ni < 4; ni++)
#pragma unroll
            for (int r = 0; r < 4; r++) {
                int ii = i0 + C_ROW(wm, mi, r);
                int e  = e0 + C_COL(wn, ni, r);      // e = d*3 + c
                int cc = e % 3;
                int dd = e / 3;
                int m  = b * N_ + ii;
                g_o2[((size_t)cc * BN + m) * DI + h * 64 + dd] =
                    acc[(mi * 4 + ni) * 4 + r];
            }
}

// ---------------------------------------------------------------------------
// Kernel 5: final projection. grid (32, 2, 3). Writes d_out (B,N,C,3).
// ---------------------------------------------------------------------------
__global__ __launch_bounds__(256) void out_kernel(const float* __restrict__ Wo,
                                                  float* __restrict__ out) {
    int c = blockIdx.z;
    const float* A = g_o2 + (size_t)c * BN * DI;

    int m0 = blockIdx.x * 128, o0 = blockIdx.y * 128;
    float acc[4 * 4 * 4];
    gemm_fp16x3_core<128, 2, 4, true>(A, Wo, DI, DI, DI, m0, o0, acc);

    const int lane = threadIdx.x & 31, warp = threadIdx.x >> 5;
    const int g = lane >> 2, tg = lane & 3;
    const int wm = (warp % 2) * 64, wn = (warp / 2) * 32;
#pragma unroll
    for (int mi = 0; mi < 4; mi++)
#pragma unroll
        for (int ni = 0; ni < 4; ni++)
#pragma unroll
            for (int r = 0; r < 4; r++) {
                int m = m0 + C_ROW(wm, mi, r);
                int o = o0 + C_COL(wn, ni, r);
                out[((size_t)m * C_ + o) * COOR + c] = acc[(mi * 4 + ni) * 4 + r];
            }
}

// ---------------------------------------------------------------------------
extern "C" void kernel_launch(void* const* d_in, const int* in_sizes, int n_in,
                              void* d_out, int out_size) {
    const float* x  = (const float*)d_in[0];
    const float* Wq = (const float*)d_in[1];
    const float* Wk = (const float*)d_in[2];
    const float* Wv = (const float*)d_in[3];
    const float* Wo = (const float*)d_in[4];
    float* out = (float*)d_out;

    {
        int total = COOR * BN * C_;
        transpose_x_kernel<<<(total + 255) / 256, 256>>>(x);
    }
    {
        dim3 grid(BN / 128, DI / 128, 9);
        qkv_kernel<<<grid, 256>>>(Wq, Wk, Wv);
    }
    {
        dim3 grid(N_ / 128, N_ / 128, BH);
        score_kernel<<<grid, 256>>>();
    }
    {
        softmax_kernel<<<BH * N_, 256>>>();
    }
    {
        dim3 grid(N_ / 128, E_ / 64, BH);
        pv_kernel<<<grid, 256>>>();
    }
    {
        dim3 grid(BN / 128, C_ / 128, COOR);
        out_kernel<<<grid, 256>>>(Wo, out);
    }
}

// round 9
// speedup vs baseline: 2.0621x; 1.3330x over previous
#include <cuda_runtime.h>
#include <cuda_fp16.h>
#include <cstdint>

// Problem constants
#define B_    2
#define N_    2048
#define C_    256
#define COOR  3
#define H_    8
#define D_    64
#define E_    192      // D_*COOR
#define DI    512      // dim_inner = H_*D_
#define BN    4096     // B_*N_
#define BH    16       // B_*H_

// Scratch (device globals — no runtime allocation)
// Split-format arrays hold (hi2, lo2) packed fp16x2 pairs per 2 adjacent K elems.
__device__ uint2 g_xt2[(size_t)COOR * BN * (C_ / 2)];        // [c][m][ipair]
__device__ uint2 g_w2 [(size_t)3 * DI * (C_ / 2)];           // [mat][o][ipair]
__device__ uint2 g_wo2[(size_t)C_ * (DI / 2)];               // [o][ipair]
__device__ float g_q  [(size_t)BH * N_ * E_];                // [bh][n][e]
__device__ float g_k  [(size_t)BH * N_ * E_];
__device__ float g_v  [(size_t)BH * N_ * E_];
__device__ uint2 g_q2 [(size_t)BH * N_ * (E_ / 2)];          // [bh][n][epair]
__device__ uint2 g_k2 [(size_t)BH * N_ * (E_ / 2)];
__device__ uint2 g_v2 [(size_t)BH * E_ * (N_ / 2)];          // [bh][e][npair]
__device__ float g_s  [(size_t)BH * N_ * N_];                // 256 MB
__device__ uint2 g_p2 [(size_t)BH * N_ * (N_ / 2)];          // [bh][i][jpair]
__device__ float g_o2 [(size_t)COOR * BN * DI];              // [c][m][di]
__device__ uint2 g_o22[(size_t)COOR * BN * (DI / 2)];        // [c][m][dipair]

// ---------------------------------------------------------------------------
// fp16 helpers
// ---------------------------------------------------------------------------
__device__ __forceinline__ uint2 split2h(float2 v) {
    __half hx = __float2half_rn(v.x);
    __half hy = __float2half_rn(v.y);
    float lx = v.x - __half2float(hx);
    float ly = v.y - __half2float(hy);
    __half lxh = __float2half_rn(lx);
    __half lyh = __float2half_rn(ly);
    uint2 r;
    r.x = ((uint32_t)__half_as_ushort(hy) << 16) | (uint32_t)__half_as_ushort(hx);
    r.y = ((uint32_t)__half_as_ushort(lyh) << 16) | (uint32_t)__half_as_ushort(lxh);
    return r;
}

__device__ __forceinline__ void mma_fp16_k16(float* c, const uint32_t* a, const uint32_t* b) {
    asm volatile(
        "mma.sync.aligned.m16n8k16.row.col.f32.f16.f16.f32 "
        "{%0,%1,%2,%3},{%4,%5,%6,%7},{%8,%9},{%0,%1,%2,%3};"
        : "+f"(c[0]), "+f"(c[1]), "+f"(c[2]), "+f"(c[3])
        : "r"(a[0]), "r"(a[1]), "r"(a[2]), "r"(a[3]), "r"(b[0]), "r"(b[1]));
}

// XOR swizzle for uint2 [16][stride] arrays (stride % 16 == 4)
__device__ __forceinline__ int SW(int kp, int m) {
    return m ^ (kp & 7) ^ ((kp & 8) >> 2);
}

// ---------------------------------------------------------------------------
// Core: C[128 x BNT] = A * B^T, pre-split operands (K-major pairs, uint2).
// A2: [row][kpair] with row stride lda2; B2: [row][kpair], stride ldb2.
// K2 = K/2 pairs, staged 16 pairs (K=32) per iteration.
// ---------------------------------------------------------------------------
template<int BNT, int WARPS_M, int WARPS_N>
__device__ __forceinline__ void gemm_split_core(
    const uint2* __restrict__ A2, const uint2* __restrict__ B2,
    int K2, int lda2, int ldb2, int m0, int n0, float* acc)
{
    constexpr int WM = 128 / WARPS_M;
    constexpr int WN = BNT / WARPS_N;
    constexpr int MI = WM / 16;
    constexpr int NI = WN / 8;

    __shared__ uint2 As2[16][132];
    __shared__ uint2 Bs2[16][BNT + 4];

    const int tid  = threadIdx.x;
    const int lane = tid & 31;
    const int warp = tid >> 5;
    const int g    = lane >> 2;
    const int tg   = lane & 3;
    const int wm   = (warp % WARPS_M) * WM;
    const int wn   = (warp / WARPS_M) * WN;

#pragma unroll
    for (int i = 0; i < MI * NI * 4; i++) acc[i] = 0.f;

    for (int kk2 = 0; kk2 < K2; kk2 += 16) {
        // ---- stage A tile: 128 rows x 8 uint4 (16 pairs) ----
#pragma unroll
        for (int it = 0; it < 4; ++it) {
            int linear = tid + 256 * it;           // 1024 uint4
            int m = linear >> 3, kq = linear & 7;
            uint4 w = *reinterpret_cast<const uint4*>(
                A2 + (size_t)(m0 + m) * lda2 + kk2 + 2 * kq);
            int kp0 = 2 * kq, kp1 = 2 * kq + 1;
            As2[kp0][SW(kp0, m)] = make_uint2(w.x, w.y);
            As2[kp1][SW(kp1, m)] = make_uint2(w.z, w.w);
        }
        // ---- stage B tile: BNT rows x 8 uint4 ----
#pragma unroll
        for (int it = 0; it < BNT * 8 / 256; ++it) {
            int linear = tid + 256 * it;
            int n = linear >> 3, kq = linear & 7;
            uint4 w = *reinterpret_cast<const uint4*>(
                B2 + (size_t)(n0 + n) * ldb2 + kk2 + 2 * kq);
            int kp0 = 2 * kq, kp1 = 2 * kq + 1;
            Bs2[kp0][SW(kp0, n)] = make_uint2(w.x, w.y);
            Bs2[kp1][SW(kp1, n)] = make_uint2(w.z, w.w);
        }
        __syncthreads();

#pragma unroll
        for (int kc = 0; kc < 2; ++kc) {
            const int kp0 = kc * 8 + tg;
            const int kp1 = kc * 8 + tg + 4;
            uint32_t ahi[MI][4], alo[MI][4], bhi[NI][2], blo[NI][2];
#pragma unroll
            for (int mi = 0; mi < MI; mi++) {
                int mb = wm + mi * 16;
                uint2 p;
                p = As2[kp0][SW(kp0, mb + g)];     ahi[mi][0] = p.x; alo[mi][0] = p.y;
                p = As2[kp0][SW(kp0, mb + g + 8)]; ahi[mi][1] = p.x; alo[mi][1] = p.y;
                p = As2[kp1][SW(kp1, mb + g)];     ahi[mi][2] = p.x; alo[mi][2] = p.y;
                p = As2[kp1][SW(kp1, mb + g + 8)]; ahi[mi][3] = p.x; alo[mi][3] = p.y;
            }
#pragma unroll
            for (int ni = 0; ni < NI; ni++) {
                int nb = wn + ni * 8;
                uint2 p;
                p = Bs2[kp0][SW(kp0, nb + g)];     bhi[ni][0] = p.x; blo[ni][0] = p.y;
                p = Bs2[kp1][SW(kp1, nb + g)];     bhi[ni][1] = p.x; blo[ni][1] = p.y;
            }
#pragma unroll
            for (int mi = 0; mi < MI; mi++)
#pragma unroll
                for (int ni = 0; ni < NI; ni++) {
                    float* c = acc + (mi * NI + ni) * 4;
                    mma_fp16_k16(c, ahi[mi], bhi[ni]);
                    mma_fp16_k16(c, ahi[mi], blo[ni]);
                    mma_fp16_k16(c, alo[mi], bhi[ni]);
                }
        }
        __syncthreads();
    }
}

#define C_ROW(wm_, mi_, r_)  ((wm_) + (mi_) * 16 + g + (((r_) >> 1) & 1) * 8)
#define C_COL(wn_, ni_, r_)  ((wn_) + (ni_) * 8 + tg * 2 + ((r_) & 1))

// ---------------------------------------------------------------------------
// Kernel 0: transpose + split x -> xt2[c][m][ipair]
// ---------------------------------------------------------------------------
__global__ __launch_bounds__(256) void transpose_x_split(const float* __restrict__ x) {
    int idx = blockIdx.x * 256 + threadIdx.x;       // over 3*4096*128
    if (idx < COOR * BN * (C_ / 2)) {
        int ip = idx & 127;
        int m  = (idx >> 7) & 4095;
        int c  = idx >> 19;
        float2 v;
        v.x = x[((size_t)m * C_ + 2 * ip)     * COOR + c];
        v.y = x[((size_t)m * C_ + 2 * ip + 1) * COOR + c];
        g_xt2[idx] = split2h(v);
    }
}

// ---------------------------------------------------------------------------
// Kernel 0b: split weights (Wq,Wk,Wv -> g_w2; Wo -> g_wo2)
// ---------------------------------------------------------------------------
__global__ __launch_bounds__(256) void split_w_kernel(const float* __restrict__ Wq,
                                                      const float* __restrict__ Wk,
                                                      const float* __restrict__ Wv,
                                                      const float* __restrict__ Wo) {
    int idx = blockIdx.x * 256 + threadIdx.x;
    const int NQKV = 3 * DI * (C_ / 2);
    if (idx < NQKV) {
        int ip  = idx & 127;
        int o   = (idx >> 7) & 511;
        int mat = idx >> 16;
        const float* W = (mat == 0) ? Wq : (mat == 1) ? Wk : Wv;
        float2 v;
        v.x = W[(size_t)o * C_ + 2 * ip];
        v.y = W[(size_t)o * C_ + 2 * ip + 1];
        g_w2[idx] = split2h(v);
    } else if (idx < NQKV + C_ * (DI / 2)) {
        int j  = idx - NQKV;
        int ip = j & 255;
        int o  = j >> 8;
        float2 v;
        v.x = Wo[(size_t)o * DI + 2 * ip];
        v.y = Wo[(size_t)o * DI + 2 * ip + 1];
        g_wo2[j] = split2h(v);
    }
}

// ---------------------------------------------------------------------------
// Kernel 1: QKV projection. grid (32, 4, 9)
// ---------------------------------------------------------------------------
__global__ __launch_bounds__(256) void qkv_kernel() {
    int z   = blockIdx.z;
    int mat = z / 3, c = z % 3;
    float* G = (mat == 0) ? g_q : (mat == 1) ? g_k : g_v;
    const uint2* A2 = g_xt2 + (size_t)c * BN * (C_ / 2);
    const uint2* B2 = g_w2 + (size_t)mat * DI * (C_ / 2);

    int m0 = blockIdx.x * 128, n0 = blockIdx.y * 128;
    float acc[4 * 4 * 4];
    gemm_split_core<128, 2, 4>(A2, B2, C_ / 2, C_ / 2, C_ / 2, m0, n0, acc);

    const int lane = threadIdx.x & 31, warp = threadIdx.x >> 5;
    const int g = lane >> 2, tg = lane & 3;
    const int wm = (warp % 2) * 64, wn = (warp / 2) * 32;
#pragma unroll
    for (int mi = 0; mi < 4; mi++)
#pragma unroll
        for (int ni = 0; ni < 4; ni++)
#pragma unroll
            for (int r = 0; r < 4; r++) {
                int m = m0 + C_ROW(wm, mi, r);
                int o = n0 + C_COL(wn, ni, r);
                int bb = m >> 11, n = m & (N_ - 1);
                int h = o >> 6, d = o & 63;
                G[(size_t)((bb * H_ + h) * N_ + n) * E_ + d * COOR + c] =
                    acc[(mi * 4 + ni) * 4 + r];
            }
}

// ---------------------------------------------------------------------------
// Kernel 1b: split q,k along e -> q2,k2 [bh][n][epair]
// ---------------------------------------------------------------------------
__global__ __launch_bounds__(256) void split_qk_kernel() {
    int idx = blockIdx.x * 256 + threadIdx.x;       // over 2 * 16*2048*96
    const int PER = BH * N_ * (E_ / 2);
    if (idx < 2 * PER) {
        int which = idx >= PER;
        int j = which ? idx - PER : idx;
        const float* src = which ? g_k : g_q;
        float2 v;
        v.x = src[(size_t)2 * j];
        v.y = src[(size_t)2 * j + 1];
        (which ? g_k2 : g_q2)[j] = split2h(v);
    }
}

// ---------------------------------------------------------------------------
// Kernel 1c: transpose + split v -> v2 [bh][e][npair]. grid (32, 3, 16)
// ---------------------------------------------------------------------------
__global__ __launch_bounds__(256) void split_v_kernel() {
    __shared__ float vs[64][65];
    int bh = blockIdx.z;
    int nb0 = blockIdx.x * 64, e0 = blockIdx.y * 64;
    int tid = threadIdx.x;
    const float* V = g_v + (size_t)bh * N_ * E_;
#pragma unroll
    for (int it = 0; it < 16; ++it) {
        int linear = tid + 256 * it;
        int row = linear >> 6, col = linear & 63;
        vs[row][col] = V[(size_t)(nb0 + row) * E_ + e0 + col];
    }
    __syncthreads();
    uint2* V2 = g_v2 + (size_t)bh * E_ * (N_ / 2);
#pragma unroll
    for (int it = 0; it < 8; ++it) {
        int linear = tid + 256 * it;                // 64 e x 32 np
        int e_loc = linear >> 5, np = linear & 31;
        float2 v = make_float2(vs[2 * np][e_loc], vs[2 * np + 1][e_loc]);
        V2[(size_t)(e0 + e_loc) * (N_ / 2) + nb0 / 2 + np] = split2h(v);
    }
}

// ---------------------------------------------------------------------------
// Kernel 2: S = scale * Q K^T per bh. grid (16, 16, 16)
// ---------------------------------------------------------------------------
__global__ __launch_bounds__(256) void score_kernel() {
    int bh = blockIdx.z;
    const uint2* Q2 = g_q2 + (size_t)bh * N_ * (E_ / 2);
    const uint2* K2 = g_k2 + (size_t)bh * N_ * (E_ / 2);
    float*       S  = g_s + (size_t)bh * N_ * N_;

    int i0 = blockIdx.x * 128, j0 = blockIdx.y * 128;
    float acc[4 * 4 * 4];
    gemm_split_core<128, 2, 4>(Q2, K2, E_ / 2, E_ / 2, E_ / 2, i0, j0, acc);

    const float scale = 0.07216878364870323f;  // 192^-0.5
    const int lane = threadIdx.x & 31, warp = threadIdx.x >> 5;
    const int g = lane >> 2, tg = lane & 3;
    const int wm = (warp % 2) * 64, wn = (warp / 2) * 32;
#pragma unroll
    for (int mi = 0; mi < 4; mi++)
#pragma unroll
        for (int ni = 0; ni < 4; ni++)
#pragma unroll
            for (int r = 0; r < 4; r++) {
                int ii = i0 + C_ROW(wm, mi, r);
                int jj = j0 + C_COL(wn, ni, r);
                S[(size_t)ii * N_ + jj] = acc[(mi * 4 + ni) * 4 + r] * scale;
            }
}

// ---------------------------------------------------------------------------
// Kernel 3: row softmax; reads fp32 S, writes split P2 [bh][i][jpair]
// ---------------------------------------------------------------------------
__global__ __launch_bounds__(256) void softmax_kernel() {
    __shared__ float red[8];
    __shared__ float bval;
    size_t row = blockIdx.x;
    const float2* Srow = reinterpret_cast<const float2*>(g_s + row * (size_t)N_);
    uint2* Prow = g_p2 + row * (size_t)(N_ / 2);
    int tid = threadIdx.x;
    int lane = tid & 31, w = tid >> 5;

    float2 v[4];
    float mx = -1e30f;
#pragma unroll
    for (int j = 0; j < 4; j++) {
        v[j] = Srow[tid + 256 * j];
        mx = fmaxf(mx, fmaxf(v[j].x, v[j].y));
    }
#pragma unroll
    for (int o = 16; o; o >>= 1) mx = fmaxf(mx, __shfl_xor_sync(0xffffffffu, mx, o));
    if (lane == 0) red[w] = mx;
    __syncthreads();
    if (tid == 0) {
        float m2 = red[0];
#pragma unroll
        for (int i = 1; i < 8; i++) m2 = fmaxf(m2, red[i]);
        bval = m2;
    }
    __syncthreads();
    mx = bval;

    float s = 0.f;
#pragma unroll
    for (int j = 0; j < 4; j++) {
        v[j].x = __expf(v[j].x - mx);
        v[j].y = __expf(v[j].y - mx);
        s += v[j].x + v[j].y;
    }
#pragma unroll
    for (int o = 16; o; o >>= 1) s += __shfl_xor_sync(0xffffffffu, s, o);
    __syncthreads();
    if (lane == 0) red[w] = s;
    __syncthreads();
    if (tid == 0) {
        float t = 0.f;
#pragma unroll
        for (int i = 0; i < 8; i++) t += red[i];
        bval = 1.f / t;
    }
    __syncthreads();
    float inv = bval;
#pragma unroll
    for (int j = 0; j < 4; j++)
        Prow[tid + 256 * j] = split2h(make_float2(v[j].x * inv, v[j].y * inv));
}

// ---------------------------------------------------------------------------
// Kernel 4: O = P2 @ V2^T per bh. grid (16, 3, 16). BNT=64 rows of e.
// ---------------------------------------------------------------------------
__global__ __launch_bounds__(256) void pv_kernel() {
    int bh = blockIdx.z;
    const uint2* P2 = g_p2 + (size_t)bh * N_ * (N_ / 2);
    const uint2* V2 = g_v2 + (size_t)bh * E_ * (N_ / 2);

    int i0 = blockIdx.x * 128, e0 = blockIdx.y * 64;
    float acc[2 * 4 * 4];
    gemm_split_core<64, 4, 2>(P2, V2, N_ / 2, N_ / 2, N_ / 2, i0, e0, acc);

    const int lane = threadIdx.x & 31, warp = threadIdx.x >> 5;
    const int g = lane >> 2, tg = lane & 3;
    const int wm = (warp % 4) * 32, wn = (warp / 4) * 32;
    int b = bh >> 3, h = bh & 7;
#pragma unroll
    for (int mi = 0; mi < 2; mi++)
#pragma unroll
        for (int ni = 0; ni < 4; ni++)
#pragma unroll
            for (int r = 0; r < 4; r++) {
                int ii = i0 + C_ROW(wm, mi, r);
                int e  = e0 + C_COL(wn, ni, r);      // e = d*3 + c
                int cc = e % 3;
                int dd = e / 3;
                int m  = b * N_ + ii;
                g_o2[((size_t)cc * BN + m) * DI + h * 64 + dd] =
                    acc[(mi * 4 + ni) * 4 + r];
            }
}

// ---------------------------------------------------------------------------
// Kernel 4b: split o2 -> o22 [c][m][dipair]
// ---------------------------------------------------------------------------
__global__ __launch_bounds__(256) void split_o2_kernel() {
    int idx = blockIdx.x * 256 + threadIdx.x;       // over 3*4096*256
    if (idx < COOR * BN * (DI / 2)) {
        float2 v;
        v.x = g_o2[(size_t)2 * idx];
        v.y = g_o2[(size_t)2 * idx + 1];
        g_o22[idx] = split2h(v);
    }
}

// ---------------------------------------------------------------------------
// Kernel 5: final projection. grid (32, 2, 3). Writes d_out (B,N,C,3).
// ---------------------------------------------------------------------------
__global__ __launch_bounds__(256) void out_kernel(float* __restrict__ out) {
    int c = blockIdx.z;
    const uint2* A2 = g_o22 + (size_t)c * BN * (DI / 2);

    int m0 = blockIdx.x * 128, o0 = blockIdx.y * 128;
    float acc[4 * 4 * 4];
    gemm_split_core<128, 2, 4>(A2, g_wo2, DI / 2, DI / 2, DI / 2, m0, o0, acc);

    const int lane = threadIdx.x & 31, warp = threadIdx.x >> 5;
    const int g = lane >> 2, tg = lane & 3;
    const int wm = (warp % 2) * 64, wn = (warp / 2) * 32;
#pragma unroll
    for (int mi = 0; mi < 4; mi++)
#pragma unroll
        for (int ni = 0; ni < 4; ni++)
#pragma unroll
            for (int r = 0; r < 4; r++) {
                int m = m0 + C_ROW(wm, mi, r);
                int o = o0 + C_COL(wn, ni, r);
                out[((size_t)m * C_ + o) * COOR + c] = acc[(mi * 4 + ni) * 4 + r];
            }
}

// ---------------------------------------------------------------------------
extern "C" void kernel_launch(void* const* d_in, const int* in_sizes, int n_in,
                              void* d_out, int out_size) {
    const float* x  = (const float*)d_in[0];
    const float* Wq = (const float*)d_in[1];
    const float* Wk = (const float*)d_in[2];
    const float* Wv = (const float*)d_in[3];
    const float* Wo = (const float*)d_in[4];
    float* out = (float*)d_out;

    {
        int total = COOR * BN * (C_ / 2);
        transpose_x_split<<<(total + 255) / 256, 256>>>(x);
    }
    {
        int total = 3 * DI * (C_ / 2) + C_ * (DI / 2);
        split_w_kernel<<<(total + 255) / 256, 256>>>(Wq, Wk, Wv, Wo);
    }
    {
        dim3 grid(BN / 128, DI / 128, 9);
        qkv_kernel<<<grid, 256>>>();
    }
    {
        int total = 2 * BH * N_ * (E_ / 2);
        split_qk_kernel<<<(total + 255) / 256, 256>>>();
    }
    {
        dim3 grid(N_ / 64, E_ / 64, BH);
        split_v_kernel<<<grid, 256>>>();
    }
    {
        dim3 grid(N_ / 128, N_ / 128, BH);
        score_kernel<<<grid, 256>>>();
    }
    {
        softmax_kernel<<<BH * N_, 256>>>();
    }
    {
        dim3 grid(N_ / 128, E_ / 64, BH);
        pv_kernel<<<grid, 256>>>();
    }
    {
        int total = COOR * BN * (DI / 2);
        split_o2_kernel<<<(total + 255) / 256, 256>>>();
    }
    {
        dim3 grid(BN / 128, C_ / 128, COOR);
        out_kernel<<<grid, 256>>>(out);
    }
}